// round 2
// baseline (speedup 1.0000x reference)
#include <cuda_runtime.h>
#include <cuda_bf16.h>
#include <mma.h>
#include <cstdint>

using namespace nvcuda;

#define NAG  8192
#define OBSD 64
#define HID  128
#define ACTD 16

// Scratch (device globals: no allocations allowed)
__device__ float          g_h  [NAG * HID];   // fp32 encoder output
__device__ __nv_bfloat16  g_hb [NAG * HID];   // bf16 copy for tensor-core GEMM
__device__ float          g_msg[NAG * HID];   // neighbor-mean messages

// ---------------------------------------------------------------------------
// K1: h = tanh(obs @ W1 + b1), also emit bf16 copy.
// 1024 CTAs x 256 threads; one warp per agent, lane l owns cols 4l..4l+3.
// ---------------------------------------------------------------------------
__global__ void __launch_bounds__(256) k1_encoder(const float* __restrict__ obs,
                                                  const float* __restrict__ W1,
                                                  const float* __restrict__ b1) {
    __shared__ __align__(16) float sW1[OBSD * HID];   // 32 KB
    __shared__ float sObs[8][OBSD];                   // 2 KB
    const int t  = threadIdx.x;
    const int a0 = blockIdx.x * 8;

    #pragma unroll
    for (int i = 0; i < (OBSD * HID) / 256; ++i)
        sW1[i * 256 + t] = W1[i * 256 + t];
    #pragma unroll
    for (int i = 0; i < 2; ++i) {
        int idx = i * 256 + t;               // 512 obs floats
        sObs[idx >> 6][idx & 63] = obs[(size_t)(a0 + (idx >> 6)) * OBSD + (idx & 63)];
    }
    __syncthreads();

    const int w = t >> 5, l = t & 31;
    const int agent = a0 + w;
    float acc0 = 0.f, acc1 = 0.f, acc2 = 0.f, acc3 = 0.f;
    #pragma unroll 8
    for (int k = 0; k < OBSD; ++k) {
        float o = sObs[w][k];
        float4 wv = *reinterpret_cast<const float4*>(&sW1[k * HID + l * 4]);
        acc0 = fmaf(o, wv.x, acc0);
        acc1 = fmaf(o, wv.y, acc1);
        acc2 = fmaf(o, wv.z, acc2);
        acc3 = fmaf(o, wv.w, acc3);
    }
    float4 bb = *reinterpret_cast<const float4*>(&b1[l * 4]);
    float h0 = tanhf(acc0 + bb.x);
    float h1 = tanhf(acc1 + bb.y);
    float h2 = tanhf(acc2 + bb.z);
    float h3 = tanhf(acc3 + bb.w);

    const size_t off = (size_t)agent * HID + l * 4;
    float4 hv; hv.x = h0; hv.y = h1; hv.z = h2; hv.w = h3;
    *reinterpret_cast<float4*>(&g_h[off]) = hv;
    __nv_bfloat162 p0 = __floats2bfloat162_rn(h0, h1);
    __nv_bfloat162 p1 = __floats2bfloat162_rn(h2, h3);
    *reinterpret_cast<__nv_bfloat162*>(&g_hb[off])     = p0;
    *reinterpret_cast<__nv_bfloat162*>(&g_hb[off + 2]) = p1;
}

// ---------------------------------------------------------------------------
// K2: msg = (adj @ h) / max(deg,1) via bf16 WMMA, fp32 accumulate.
// 128 CTAs, each owns M-tile of 64 rows x all 128 cols. K chunks of 64.
// adj int32 -> bf16 conversion fused in the loader; deg counted for free.
// Prefetch next chunk into registers while MMAing current chunk.
// ---------------------------------------------------------------------------
__device__ __forceinline__ unsigned pack2(int a, int b) {
    return (a ? 0x3F80u : 0u) | (b ? 0x3F800000u : 0u);   // two bf16 {0,1}
}
__device__ __forceinline__ int nz4(int4 v) {
    return (v.x != 0) + (v.y != 0) + (v.z != 0) + (v.w != 0);
}

__global__ void __launch_bounds__(256) k2_msg(const int* __restrict__ adj) {
    // union: [phase 1] sA bf16[64][72] (9216B) + sB bf16[64][136] (17408B)
    //        [phase 2] sAcc float[64][132] (33792B)
    __shared__ __align__(32) unsigned char smem_raw[64 * 132 * 4];
    __shared__ int sDeg[64];
    __nv_bfloat16* sA   = reinterpret_cast<__nv_bfloat16*>(smem_raw);          // ld 72
    __nv_bfloat16* sB   = reinterpret_cast<__nv_bfloat16*>(smem_raw + 9216);   // ld 136
    float*         sAcc = reinterpret_cast<float*>(smem_raw);                  // ld 132

    const int t  = threadIdx.x;
    const int m0 = blockIdx.x * 64;
    if (t < 64) sDeg[t] = 0;

    // A loader: thread -> (row r, 16-col group cg); each loads 16 int32/chunk
    const int r  = t >> 2;
    const int cg = t & 3;
    const int4* gA = reinterpret_cast<const int4*>(adj + (size_t)(m0 + r) * NAG) + cg * 4;
    // B loader: 4x uint4 (8 bf16 each) per chunk
    const int brow = t >> 4;          // + 16*i
    const int bc16 = t & 15;
    const uint4* gB = reinterpret_cast<const uint4*>(g_hb);

    int4  ra[4];
    uint4 rb[4];
    #pragma unroll
    for (int i = 0; i < 4; ++i) ra[i] = gA[i];
    #pragma unroll
    for (int i = 0; i < 4; ++i) rb[i] = gB[(size_t)(16 * i + brow) * 16 + bc16];

    wmma::fragment<wmma::accumulator, 16, 16, 16, float> acc[2][2];
    #pragma unroll
    for (int i = 0; i < 2; ++i)
        #pragma unroll
        for (int j = 0; j < 2; ++j)
            wmma::fill_fragment(acc[i][j], 0.0f);

    const int wid = t >> 5;
    const int wm  = wid & 1;      // 2 M-blocks of 32
    const int wn  = wid >> 1;     // 4 N-blocks of 32

    int cnt = 0;
    const int NCH = NAG / 64;     // 128 K-chunks
    for (int c = 0; c < NCH; ++c) {
        // ---- stage current chunk to smem ----
        uint4 w0, w1;
        w0.x = pack2(ra[0].x, ra[0].y); w0.y = pack2(ra[0].z, ra[0].w);
        w0.z = pack2(ra[1].x, ra[1].y); w0.w = pack2(ra[1].z, ra[1].w);
        w1.x = pack2(ra[2].x, ra[2].y); w1.y = pack2(ra[2].z, ra[2].w);
        w1.z = pack2(ra[3].x, ra[3].y); w1.w = pack2(ra[3].z, ra[3].w);
        cnt += nz4(ra[0]) + nz4(ra[1]) + nz4(ra[2]) + nz4(ra[3]);
        uint4* dA = reinterpret_cast<uint4*>(&sA[r * 72 + cg * 16]);
        dA[0] = w0; dA[1] = w1;
        #pragma unroll
        for (int i = 0; i < 4; ++i)
            *reinterpret_cast<uint4*>(&sB[(16 * i + brow) * 136 + bc16 * 8]) = rb[i];
        __syncthreads();

        // ---- prefetch next chunk (LDG latency hidden under MMA) ----
        if (c + 1 < NCH) {
            const int4*  gAn = gA + (c + 1) * 16;
            const uint4* gBn = gB + (size_t)(c + 1) * 64 * 16;
            #pragma unroll
            for (int i = 0; i < 4; ++i) ra[i] = gAn[i];
            #pragma unroll
            for (int i = 0; i < 4; ++i) rb[i] = gBn[(16 * i + brow) * 16 + bc16];
        }

        // ---- MMA over the 4 K-steps of this chunk ----
        #pragma unroll
        for (int ks = 0; ks < 4; ++ks) {
            wmma::fragment<wmma::matrix_a, 16, 16, 16, __nv_bfloat16, wmma::row_major> af[2];
            wmma::fragment<wmma::matrix_b, 16, 16, 16, __nv_bfloat16, wmma::row_major> bf[2];
            wmma::load_matrix_sync(af[0], &sA[(wm * 32) * 72 + ks * 16], 72);
            wmma::load_matrix_sync(af[1], &sA[(wm * 32 + 16) * 72 + ks * 16], 72);
            wmma::load_matrix_sync(bf[0], &sB[(ks * 16) * 136 + wn * 32], 136);
            wmma::load_matrix_sync(bf[1], &sB[(ks * 16) * 136 + wn * 32 + 16], 136);
            #pragma unroll
            for (int i = 0; i < 2; ++i)
                #pragma unroll
                for (int j = 0; j < 2; ++j)
                    wmma::mma_sync(acc[i][j], af[i], bf[j], acc[i][j]);
        }
        __syncthreads();
    }

    atomicAdd(&sDeg[r], cnt);
    #pragma unroll
    for (int i = 0; i < 2; ++i)
        #pragma unroll
        for (int j = 0; j < 2; ++j)
            wmma::store_matrix_sync(&sAcc[(wm * 32 + i * 16) * 132 + wn * 32 + j * 16],
                                    acc[i][j], 132, wmma::mem_row_major);
    __syncthreads();

    #pragma unroll
    for (int i = 0; i < 32; ++i) {
        int idx = i * 256 + t;                 // 8192 outputs
        int row = idx >> 7, col = idx & 127;
        float s = 1.0f / (float)max(sDeg[row], 1);
        g_msg[(size_t)(m0 + row) * HID + col] = sAcc[row * 132 + col] * s;
    }
}

// ---------------------------------------------------------------------------
// K3: hid = tanh([h,msg] @ W2 + b2); logits = hid @ W3 + b3.
// 128 CTAs x 64 agents; W2 fully in smem (128KB). Thread computes 4x8 hid tile.
// ---------------------------------------------------------------------------
#define K3_SMEM (4 * (32768 + 16448 + 2048 + 128 + 16))   // 205,632 B

__global__ void __launch_bounds__(256, 1) k3_actor(float* __restrict__ out,
        const float* __restrict__ W2, const float* __restrict__ b2,
        const float* __restrict__ W3, const float* __restrict__ b3) {
    extern __shared__ __align__(16) float sm[];
    float* sW2 = sm;                   // [256][128]
    float* sC  = sm + 32768;           // [64][257] combined; reused as hid [64][129]
    float* sW3 = sC + 16448;           // [128][16]
    float* sb2 = sW3 + 2048;           // [128]
    float* sb3 = sb2 + 128;            // [16]

    const int t  = threadIdx.x;
    const int a0 = blockIdx.x * 64;

    #pragma unroll 4
    for (int i = 0; i < 128; ++i) sW2[i * 256 + t] = W2[i * 256 + t];
    #pragma unroll
    for (int i = 0; i < 8; ++i)   sW3[i * 256 + t] = W3[i * 256 + t];
    if (t < 128) sb2[t] = b2[t];
    if (t < 16)  sb3[t] = b3[t];
    #pragma unroll 4
    for (int i = 0; i < 32; ++i) {
        int idx = i * 256 + t;             // 8192 (agent,col) pairs
        int a = idx >> 7, k = idx & 127;
        sC[a * 257 + k]       = g_h  [(size_t)(a0 + a) * HID + k];
        sC[a * 257 + 128 + k] = g_msg[(size_t)(a0 + a) * HID + k];
    }
    __syncthreads();

    const int ar = t >> 4;    // agents ar*4 .. ar*4+3
    const int cc = t & 15;    // cols cc*8 .. cc*8+7
    float acc[4][8];
    #pragma unroll
    for (int j = 0; j < 4; ++j)
        #pragma unroll
        for (int i = 0; i < 8; ++i) acc[j][i] = 0.f;

    #pragma unroll 2
    for (int k = 0; k < 2 * HID; ++k) {
        float4 w0 = *reinterpret_cast<const float4*>(&sW2[k * 128 + cc * 8]);
        float4 w1 = *reinterpret_cast<const float4*>(&sW2[k * 128 + cc * 8 + 4]);
        #pragma unroll
        for (int j = 0; j < 4; ++j) {
            float cv = sC[(ar * 4 + j) * 257 + k];
            acc[j][0] = fmaf(cv, w0.x, acc[j][0]);
            acc[j][1] = fmaf(cv, w0.y, acc[j][1]);
            acc[j][2] = fmaf(cv, w0.z, acc[j][2]);
            acc[j][3] = fmaf(cv, w0.w, acc[j][3]);
            acc[j][4] = fmaf(cv, w1.x, acc[j][4]);
            acc[j][5] = fmaf(cv, w1.y, acc[j][5]);
            acc[j][6] = fmaf(cv, w1.z, acc[j][6]);
            acc[j][7] = fmaf(cv, w1.w, acc[j][7]);
        }
    }
    __syncthreads();                      // all comb reads done; reuse sC as hid
    float* sH = sC;                       // [64][129]
    #pragma unroll
    for (int j = 0; j < 4; ++j) {
        int a = ar * 4 + j;
        #pragma unroll
        for (int i = 0; i < 8; ++i) {
            int ccol = cc * 8 + i;
            sH[a * 129 + ccol] = tanhf(acc[j][i] + sb2[ccol]);
        }
    }
    __syncthreads();

    const int a  = t >> 2;   // 0..63
    const int cq = t & 3;    // col quad
    float4 lg; lg.x = 0.f; lg.y = 0.f; lg.z = 0.f; lg.w = 0.f;
    #pragma unroll 8
    for (int k = 0; k < HID; ++k) {
        float hv  = sH[a * 129 + k];
        float4 w3 = *reinterpret_cast<const float4*>(&sW3[k * 16 + cq * 4]);
        lg.x = fmaf(hv, w3.x, lg.x);
        lg.y = fmaf(hv, w3.y, lg.y);
        lg.z = fmaf(hv, w3.z, lg.z);
        lg.w = fmaf(hv, w3.w, lg.w);
    }
    lg.x += sb3[cq * 4 + 0];
    lg.y += sb3[cq * 4 + 1];
    lg.z += sb3[cq * 4 + 2];
    lg.w += sb3[cq * 4 + 3];
    *reinterpret_cast<float4*>(&out[(size_t)(a0 + a) * ACTD + cq * 4]) = lg;
}

// ---------------------------------------------------------------------------
extern "C" void kernel_launch(void* const* d_in, const int* in_sizes, int n_in,
                              void* d_out, int out_size) {
    const float* obs = (const float*)d_in[0];
    const int*   adj = (const int*)  d_in[1];
    const float* W1  = (const float*)d_in[2];
    const float* b1  = (const float*)d_in[3];
    const float* W2  = (const float*)d_in[4];
    const float* b2  = (const float*)d_in[5];
    const float* W3  = (const float*)d_in[6];
    const float* b3  = (const float*)d_in[7];
    float* out = (float*)d_out;

    cudaFuncSetAttribute(k3_actor, cudaFuncAttributeMaxDynamicSharedMemorySize, K3_SMEM);

    k1_encoder<<<NAG / 8, 256>>>(obs, W1, b1);
    k2_msg    <<<NAG / 64, 256>>>(adj);
    k3_actor  <<<NAG / 64, 256, K3_SMEM>>>(out, W2, b2, W3, b3);
}